// round 10
// baseline (speedup 1.0000x reference)
#include <cuda_runtime.h>

#define BATCH   4
#define NPTS    32768
#define NQ      2048
#define KNN     16
#define QSTRIDE (NPTS / NQ)      // 16
#define TILE    2048
#define WARPS   8
#define NTHREADS (WARPS * 32)
#define CHUNK   8                // lane-iterations between tau refreshes

__global__ __launch_bounds__(NTHREADS)
void knn_kernel(const float* __restrict__ xyz,
                float* __restrict__ out)      // f32: [idx 131072][pts 24576]
{
    __shared__ float s[TILE * 3];

    const int lane = threadIdx.x & 31;
    const int warp = threadIdx.x >> 5;
    const int blocksPerBatch = NQ / WARPS;              // 256
    const int b  = blockIdx.x / blocksPerBatch;
    const int q  = (blockIdx.x % blocksPerBatch) * WARPS + warp;

    const float* base = xyz + (size_t)b * NPTS * 3;

    const float qx = base[q * QSTRIDE * 3 + 0];
    const float qy = base[q * QSTRIDE * 3 + 1];
    const float qz = base[q * QSTRIDE * 3 + 2];

    const float FINF = __int_as_float(0x7f800000);

    float    bd[KNN];
    unsigned bi[KNN];
#pragma unroll
    for (int k = 0; k < KNN; k++) { bd[k] = FINF; bi[k] = 0xffffffffu; }
    float tau = FINF;

#pragma unroll 1
    for (int t = 0; t < NPTS / TILE; t++) {
        __syncthreads();
        {   // cooperative tile load, float4-vectorized & coalesced
            const float4* g  = (const float4*)(base + (size_t)t * TILE * 3);
            float4*       sv = (float4*)s;
#pragma unroll 1
            for (int i = threadIdx.x; i < TILE * 3 / 4; i += NTHREADS)
                sv[i] = g[i];
        }
        __syncthreads();

#pragma unroll 1
        for (int jj = 0; jj < TILE; jj += 32 * CHUNK) {
#pragma unroll
            for (int u = 0; u < CHUNK; u++) {
                const int j = jj + u * 32 + lane;
                const float x = s[3 * j + 0];
                const float y = s[3 * j + 1];
                const float z = s[3 * j + 2];
                // Bit-exact match to XLA: sub, square, (xx+yy)+zz, each
                // individually rounded — NO FMA contraction (near-tie rank
                // swaps vs the reference would blow the 1e-3 norm gate).
                const float dx = __fsub_rn(qx, x);
                const float dy = __fsub_rn(qy, y);
                const float dz = __fsub_rn(qz, z);
                const float d  = __fadd_rn(__fadd_rn(__fmul_rn(dx, dx),
                                                     __fmul_rn(dy, dy)),
                                           __fmul_rn(dz, dz));
                // tau = min over lanes of each lane's 16th-best: provable
                // upper bound on the warp-global 16th distance.
                if (d <= tau && d < bd[KNN - 1]) {
                    float    cd = d;
                    unsigned ci = (unsigned)(t * TILE + j);
#pragma unroll
                    for (int k = 0; k < KNN; k++) {
                        const bool sw = cd < bd[k];   // strict: stable ties
                        const float    td = bd[k];
                        const unsigned ti = bi[k];
                        if (sw) { bd[k] = cd; bi[k] = ci; cd = td; ci = ti; }
                    }
                }
            }
            float m = bd[KNN - 1];
#pragma unroll
            for (int o = 16; o; o >>= 1)
                m = fminf(m, __shfl_xor_sync(0xffffffffu, m, o));
            tau = m;
        }
    }

    // warp merge: 16 extract-min rounds on packed (dist_bits<<32 | idx) keys.
    // dist >= 0 -> float bits order-preserving; idx in low bits reproduces
    // top_k's lower-index-first tie-breaking exactly.
    const size_t qg   = (size_t)b * NQ + q;
    float*       oidx = out + qg * (size_t)KNN;

#pragma unroll 1
    for (int k = 0; k < KNN; k++) {
        unsigned long long key =
            ((unsigned long long)__float_as_uint(bd[0]) << 32) | (unsigned long long)bi[0];
        unsigned long long mk = key;
#pragma unroll
        for (int o = 16; o; o >>= 1) {
            unsigned long long other = __shfl_xor_sync(0xffffffffu, mk, o);
            mk = (other < mk) ? other : mk;
        }
        if (lane == 0)
            oidx[k] = (float)(unsigned)(mk & 0xffffffffu);   // exact for <2^24
        if (key == mk) {
#pragma unroll
            for (int k2 = 0; k2 < KNN - 1; k2++) { bd[k2] = bd[k2 + 1]; bi[k2] = bi[k2 + 1]; }
            bd[KNN - 1] = FINF;
            bi[KNN - 1] = 0xffffffffu;
        }
    }

    if (lane == 0) {
        float* opts = out + (size_t)BATCH * NQ * KNN + qg * 3;
        opts[0] = qx;
        opts[1] = qy;
        opts[2] = qz;
    }
}

extern "C" void kernel_launch(void* const* d_in, const int* in_sizes, int n_in,
                              void* d_out, int out_size)
{
    // select xyz by element count (4*32768*3), fallback: largest input
    int xi = 0, best = -1;
    for (int i = 0; i < n_in; i++) {
        if (in_sizes[i] == BATCH * NPTS * 3) { xi = i; best = 0x7fffffff; break; }
        if (in_sizes[i] > best) { best = in_sizes[i]; xi = i; }
    }
    const float* xyz = (const float*)d_in[xi];
    (void)out_size;

    knn_kernel<<<BATCH * NQ / WARPS, NTHREADS>>>(xyz, (float*)d_out);
}

// round 11
// speedup vs baseline: 3.7592x; 3.7592x over previous
#include <cuda_runtime.h>

#define BATCH   4
#define NPTS    32768
#define NQ      2048
#define KNN     16
#define QSTRIDE (NPTS / NQ)      // 16
#define TILE    2048
#define WARPS   8
#define NTHREADS (WARPS * 32)
#define FULLMASK 0xffffffffu

__global__ __launch_bounds__(NTHREADS)
void knn_kernel(const float* __restrict__ xyz,
                float* __restrict__ out)      // f32: [idx 131072][pts 24576]
{
    __shared__ float s[TILE * 3];

    const int lane = threadIdx.x & 31;
    const int warp = threadIdx.x >> 5;
    const int blocksPerBatch = NQ / WARPS;              // 256
    const int b  = blockIdx.x / blocksPerBatch;
    const int q  = (blockIdx.x % blocksPerBatch) * WARPS + warp;

    const float* base = xyz + (size_t)b * NPTS * 3;

    const float qx = base[q * QSTRIDE * 3 + 0];
    const float qy = base[q * QSTRIDE * 3 + 1];
    const float qz = base[q * QSTRIDE * 3 + 2];

    const float FINF = __int_as_float(0x7f800000);

    // Warp-global sorted top-16, distributed: lane l (l<16) holds the
    // l-th smallest (dist, idx) so far. Lanes 16..31 hold +inf filler.
    float    list_d = FINF;
    unsigned list_i = 0xffffffffu;
    float    kth    = FINF;        // current warp-global 16th-smallest

#pragma unroll 1
    for (int t = 0; t < NPTS / TILE; t++) {
        __syncthreads();
        {   // cooperative tile load, float4-vectorized & coalesced
            const float4* g  = (const float4*)(base + (size_t)t * TILE * 3);
            float4*       sv = (float4*)s;
#pragma unroll 1
            for (int i = threadIdx.x; i < TILE * 3 / 4; i += NTHREADS)
                sv[i] = g[i];
        }
        __syncthreads();

#pragma unroll 4
        for (int jj = 0; jj < TILE; jj += 32) {
            const int j = jj + lane;
            const float x = s[3 * j + 0];
            const float y = s[3 * j + 1];
            const float z = s[3 * j + 2];
            // Bit-exact match to XLA: sub, square, (xx+yy)+zz, individually
            // rounded, no FMA (rank swaps vs reference would fail the gate).
            const float dx = __fsub_rn(qx, x);
            const float dy = __fsub_rn(qy, y);
            const float dz = __fsub_rn(qz, z);
            const float d  = __fadd_rn(__fadd_rn(__fmul_rn(dx, dx),
                                                 __fmul_rn(dy, dy)),
                                       __fmul_rn(dz, dz));

            // Admission gate: strictly beat the warp-global 16th.
            // Warp-uniform ballot => real branch, body skipped ~90% of iters.
            unsigned hits = __ballot_sync(FULLMASK, d < kth);
            if (hits) {
                do {
                    const int src = __ffs(hits) - 1;   // lowest lane first
                    hits &= hits - 1;                  //  = lowest index first
                    const float dv = __shfl_sync(FULLMASK, d, src);
                    if (dv < kth) {                    // recheck: kth tightened
                        // insert after all elements <= dv (stable ties)
                        const unsigned bal =
                            __ballot_sync(FULLMASK, dv < list_d);
                        const int pos = __ffs(bal) - 1;        // <= 15 here
                        const float    pd = __shfl_up_sync(FULLMASK, list_d, 1);
                        const unsigned pi = __shfl_up_sync(FULLMASK, list_i, 1);
                        if (lane > pos)       { list_d = pd; list_i = pi; }
                        else if (lane == pos) {
                            list_d = dv;
                            list_i = (unsigned)(t * TILE + jj + src);
                        }
                        kth = __shfl_sync(FULLMASK, list_d, 15);
                    }
                } while (hits);
            }
        }
    }

    // Epilogue: list is already the sorted warp-global top-16.
    const size_t qg = (size_t)b * NQ + q;
    if (lane < KNN)
        out[qg * KNN + lane] = (float)list_i;          // exact for < 2^24
    if (lane == 0) {
        float* opts = out + (size_t)BATCH * NQ * KNN + qg * 3;
        opts[0] = qx;
        opts[1] = qy;
        opts[2] = qz;
    }
}

extern "C" void kernel_launch(void* const* d_in, const int* in_sizes, int n_in,
                              void* d_out, int out_size)
{
    // select xyz by element count (4*32768*3), fallback: largest input
    int xi = 0, best = -1;
    for (int i = 0; i < n_in; i++) {
        if (in_sizes[i] == BATCH * NPTS * 3) { xi = i; best = 0x7fffffff; break; }
        if (in_sizes[i] > best) { best = in_sizes[i]; xi = i; }
    }
    const float* xyz = (const float*)d_in[xi];
    (void)out_size;

    knn_kernel<<<BATCH * NQ / WARPS, NTHREADS>>>(xyz, (float*)d_out);
}

// round 12
// speedup vs baseline: 4.8829x; 1.2989x over previous
#include <cuda_runtime.h>
#include <cstdint>

#define BATCH   4
#define NPTS    32768
#define NQ      2048
#define KNN     16
#define QSTRIDE (NPTS / NQ)      // 16
#define TILE    2048
#define WARPS   8
#define NTHREADS (WARPS * 32)
#define QPW     2                // queries per warp
#define FULLMASK 0xffffffffu

#define MUL_F32X2(out, a, b) \
    asm("mul.rn.f32x2 %0, %1, %2;" : "=l"(out) : "l"(a), "l"(b))
#define ADD_F32X2(out, a, b) \
    asm("add.rn.f32x2 %0, %1, %2;" : "=l"(out) : "l"(a), "l"(b))
#define PACK_F32X2(out, lo, hi) \
    asm("mov.b64 %0, {%1, %2};" : "=l"(out) : "r"(lo), "r"(hi))
#define UNPACK_F32X2(lo, hi, in) \
    asm("mov.b64 {%0, %1}, %2;" : "=r"(lo), "=r"(hi) : "l"(in))

// Insert all balloted candidates (lowest lane = lowest index first) into the
// warp-distributed sorted top-16 (lane l < 16 holds l-th smallest).
__device__ __forceinline__ void warp_insert(unsigned hits, float d, int baseIdx,
                                            float& list_d, unsigned& list_i,
                                            float& kth, int lane)
{
    while (hits) {
        const int src = __ffs(hits) - 1;
        hits &= hits - 1;
        const float dv = __shfl_sync(FULLMASK, d, src);   // warp-uniform
        if (dv < kth) {                                   // kth may have tightened
            const unsigned bal = __ballot_sync(FULLMASK, dv < list_d);
            const int pos = __ffs(bal) - 1;               // insert after ties
            const float    pd = __shfl_up_sync(FULLMASK, list_d, 1);
            const unsigned pi = __shfl_up_sync(FULLMASK, list_i, 1);
            if (lane > pos)       { list_d = pd; list_i = pi; }
            else if (lane == pos) { list_d = dv; list_i = (unsigned)(baseIdx + src); }
            kth = __shfl_sync(FULLMASK, list_d, 15);
        }
    }
}

__global__ __launch_bounds__(NTHREADS)
void knn_kernel(const float* __restrict__ xyz,
                float* __restrict__ out)      // f32: [idx 131072][pts 24576]
{
    __shared__ float s[TILE * 3];

    const int lane = threadIdx.x & 31;
    const int warp = threadIdx.x >> 5;
    const int qPerBlock = WARPS * QPW;                   // 16
    const int blocksPerBatch = NQ / qPerBlock;           // 128
    const int b  = blockIdx.x / blocksPerBatch;
    const int q0 = (blockIdx.x % blocksPerBatch) * qPerBlock + warp * QPW;
    const int q1 = q0 + 1;

    const float* base = xyz + (size_t)b * NPTS * 3;

    const float q0x = base[q0 * QSTRIDE * 3 + 0];
    const float q0y = base[q0 * QSTRIDE * 3 + 1];
    const float q0z = base[q0 * QSTRIDE * 3 + 2];
    const float q1x = base[q1 * QSTRIDE * 3 + 0];
    const float q1y = base[q1 * QSTRIDE * 3 + 1];
    const float q1z = base[q1 * QSTRIDE * 3 + 2];

    const float FINF = __int_as_float(0x7f800000);

    float    l0d = FINF, l1d = FINF;
    unsigned l0i = 0xffffffffu, l1i = 0xffffffffu;
    float    kth0 = FINF, kth1 = FINF;

#pragma unroll 1
    for (int t = 0; t < NPTS / TILE; t++) {
        __syncthreads();
        {   // cooperative tile load, float4-vectorized & coalesced
            const float4* g  = (const float4*)(base + (size_t)t * TILE * 3);
            float4*       sv = (float4*)s;
#pragma unroll 1
            for (int i = threadIdx.x; i < TILE * 3 / 4; i += NTHREADS)
                sv[i] = g[i];
        }
        __syncthreads();

#pragma unroll 8
        for (int jj = 0; jj < TILE; jj += 32) {
            const int j = jj + lane;
            const float x = s[3 * j + 0];
            const float y = s[3 * j + 1];
            const float z = s[3 * j + 2];

            // Scalar subs (individually rounded), then packed f32x2
            // mul/add: per-half IEEE rn identical to scalar — the whole
            // chain stays bit-exact vs XLA ((dx*dx+dy*dy)+dz*dz, no FMA).
            const float dx0 = __fsub_rn(q0x, x), dx1 = __fsub_rn(q1x, x);
            const float dy0 = __fsub_rn(q0y, y), dy1 = __fsub_rn(q1y, y);
            const float dz0 = __fsub_rn(q0z, z), dz1 = __fsub_rn(q1z, z);

            uint64_t vx, vy, vz, sx, sy, sz, sxy, sd;
            PACK_F32X2(vx, __float_as_uint(dx0), __float_as_uint(dx1));
            PACK_F32X2(vy, __float_as_uint(dy0), __float_as_uint(dy1));
            PACK_F32X2(vz, __float_as_uint(dz0), __float_as_uint(dz1));
            MUL_F32X2(sx, vx, vx);
            MUL_F32X2(sy, vy, vy);
            MUL_F32X2(sz, vz, vz);
            ADD_F32X2(sxy, sx, sy);
            ADD_F32X2(sd, sxy, sz);

            unsigned d0u, d1u;
            UNPACK_F32X2(d0u, d1u, sd);
            const float d0 = __uint_as_float(d0u);
            const float d1 = __uint_as_float(d1u);

            const bool p0 = d0 < kth0;
            const bool p1 = d1 < kth1;
            // warp-uniform gate -> real branch; body is rare (~240/warp total)
            if (__ballot_sync(FULLMASK, p0 | p1)) {
                const unsigned h0 = __ballot_sync(FULLMASK, p0);
                const unsigned h1 = __ballot_sync(FULLMASK, p1);
                if (h0) warp_insert(h0, d0, t * TILE + jj, l0d, l0i, kth0, lane);
                if (h1) warp_insert(h1, d1, t * TILE + jj, l1d, l1i, kth1, lane);
            }
        }
    }

    // Epilogue: lists are already the sorted warp-global top-16s.
    const size_t qg0 = (size_t)b * NQ + q0;
    const size_t qg1 = (size_t)b * NQ + q1;
    if (lane < KNN) {
        out[qg0 * KNN + lane] = (float)l0i;     // exact for < 2^24
        out[qg1 * KNN + lane] = (float)l1i;
    }
    if (lane == 0) {
        float* op0 = out + (size_t)BATCH * NQ * KNN + qg0 * 3;
        float* op1 = out + (size_t)BATCH * NQ * KNN + qg1 * 3;
        op0[0] = q0x; op0[1] = q0y; op0[2] = q0z;
        op1[0] = q1x; op1[1] = q1y; op1[2] = q1z;
    }
}

extern "C" void kernel_launch(void* const* d_in, const int* in_sizes, int n_in,
                              void* d_out, int out_size)
{
    // select xyz by element count (4*32768*3), fallback: largest input
    int xi = 0, best = -1;
    for (int i = 0; i < n_in; i++) {
        if (in_sizes[i] == BATCH * NPTS * 3) { xi = i; best = 0x7fffffff; break; }
        if (in_sizes[i] > best) { best = in_sizes[i]; xi = i; }
    }
    const float* xyz = (const float*)d_in[xi];
    (void)out_size;

    knn_kernel<<<BATCH * NQ / (WARPS * QPW), NTHREADS>>>(xyz, (float*)d_out);
}